// round 2
// baseline (speedup 1.0000x reference)
#include <cuda_runtime.h>
#include <math.h>

// Problem dims (fixed)
#define B_SZ 4
#define L_SZ 4096
#define DM   1024
#define DS   256
#define DH   4096
#define M_ROWS (B_SZ * L_SZ)   // 16384
#define CH     64              // scan chunk length
#define NCHUNK (L_SZ / CH)     // 64

// ---------------- scratch (device globals; no allocations allowed) ----------
__device__ float  g_Bu_re[(size_t)M_ROWS * DS];
__device__ float  g_Bu_im[(size_t)M_ROWS * DS];
__device__ float  g_sr  [(size_t)M_ROWS * DS];
__device__ float  g_si  [(size_t)M_ROWS * DS];
__device__ float  g_y   [(size_t)M_ROWS * DM];
__device__ float  g_h   [(size_t)M_ROWS * DH];
__device__ float2 g_lam[DS];
__device__ float  g_gamma[DS];
__device__ float2 g_final[B_SZ * NCHUNK * DS];
__device__ float2 g_carry[B_SZ * NCHUNK * DS];

__device__ __forceinline__ float2 cmul(float2 a, float2 b) {
    return make_float2(a.x * b.x - a.y * b.y, a.x * b.y + a.y * b.x);
}

// ---------------- precompute lam / gamma ------------------------------------
__global__ void precompute_k(const float* __restrict__ nu_log,
                             const float* __restrict__ theta_log) {
    int n = threadIdx.x;
    float nu  = expf(nu_log[n]);
    float th  = expf(theta_log[n]);
    float mag = expf(-nu);               // |lam|
    g_lam[n]   = make_float2(mag * cosf(th), mag * sinf(th));
    g_gamma[n] = sqrtf(fmaxf(0.f, 1.f - mag * mag));
}

// ---------------- GEMM: C[M,N] = op(A[M,K] x B), fp32, 128x128x8 tiles ------
// TN: B is [N,K] row-major (B^T multiply).  NN: B is [K,N] row-major.
enum { EPI_STORE = 0, EPI_ADD = 1, EPI_COLSCALE = 2, EPI_GELU = 3, EPI_RESID = 4 };

template<bool TN, int EPI>
__global__ __launch_bounds__(256, 2)
void gemm_k(const float* __restrict__ A, const float* __restrict__ Bm,
            float* __restrict__ C, int M, int N, int K, float alpha,
            const float* __restrict__ colscale,
            const float* __restrict__ X,
            const float* __restrict__ res_logit)
{
    __shared__ float As[8][128];
    __shared__ float Bs[8][128];

    const int tid = threadIdx.x;
    const int m0 = blockIdx.y * 128;
    const int n0 = blockIdx.x * 128;
    const int tx = tid & 15;      // N-direction thread coord
    const int ty = tid >> 4;      // M-direction thread coord

    // loader coords
    const int lrow = tid >> 1;          // 0..127
    const int lcol = (tid & 1) * 4;     // 0 or 4
    const int bk   = tid >> 5;          // 0..7   (NN B loader)
    const int bn   = (tid & 31) * 4;    // 0..124 (NN B loader)

    const float* Ap = A + (size_t)(m0 + lrow) * K + lcol;
    const float* Bp = TN ? (Bm + (size_t)(n0 + lrow) * K + lcol)
                         : (Bm + (size_t)bk * N + n0 + bn);

    float acc[8][8];
#pragma unroll
    for (int i = 0; i < 8; i++)
#pragma unroll
        for (int j = 0; j < 8; j++) acc[i][j] = 0.f;

    for (int k0 = 0; k0 < K; k0 += 8) {
        float4 av = *(const float4*)(Ap + k0);
        As[lcol + 0][lrow] = av.x; As[lcol + 1][lrow] = av.y;
        As[lcol + 2][lrow] = av.z; As[lcol + 3][lrow] = av.w;
        if (TN) {
            float4 bv = *(const float4*)(Bp + k0);
            Bs[lcol + 0][lrow] = bv.x; Bs[lcol + 1][lrow] = bv.y;
            Bs[lcol + 2][lrow] = bv.z; Bs[lcol + 3][lrow] = bv.w;
        } else {
            float4 bv = *(const float4*)(Bp + (size_t)k0 * N);
            *(float4*)&Bs[bk][bn] = bv;
        }
        __syncthreads();
#pragma unroll
        for (int kk = 0; kk < 8; kk++) {
            float4 a0 = *(const float4*)&As[kk][ty * 8];
            float4 a1 = *(const float4*)&As[kk][ty * 8 + 4];
            float4 b0 = *(const float4*)&Bs[kk][tx * 8];
            float4 b1 = *(const float4*)&Bs[kk][tx * 8 + 4];
            float ar[8] = {a0.x, a0.y, a0.z, a0.w, a1.x, a1.y, a1.z, a1.w};
            float br[8] = {b0.x, b0.y, b0.z, b0.w, b1.x, b1.y, b1.z, b1.w};
#pragma unroll
            for (int i = 0; i < 8; i++)
#pragma unroll
                for (int j = 0; j < 8; j++)
                    acc[i][j] = fmaf(ar[i], br[j], acc[i][j]);
        }
        __syncthreads();
    }

    float sig = 0.f;
    if (EPI == EPI_RESID) sig = 1.f / (1.f + expf(-res_logit[0]));

#pragma unroll
    for (int i = 0; i < 8; i++) {
        size_t row = (size_t)(m0 + ty * 8 + i) * N;
#pragma unroll
        for (int jj = 0; jj < 2; jj++) {
            int n = n0 + tx * 8 + jj * 4;
            float v0 = acc[i][jj * 4 + 0], v1 = acc[i][jj * 4 + 1];
            float v2 = acc[i][jj * 4 + 2], v3 = acc[i][jj * 4 + 3];
            float4 o;
            if (EPI == EPI_STORE) {
                o = make_float4(alpha * v0, alpha * v1, alpha * v2, alpha * v3);
            } else if (EPI == EPI_ADD) {
                float4 old = *(const float4*)(C + row + n);
                o = make_float4(old.x + alpha * v0, old.y + alpha * v1,
                                old.z + alpha * v2, old.w + alpha * v3);
            } else if (EPI == EPI_COLSCALE) {
                o = make_float4(colscale[n + 0] * v0, colscale[n + 1] * v1,
                                colscale[n + 2] * v2, colscale[n + 3] * v3);
            } else if (EPI == EPI_GELU) {
                float vv[4] = {v0, v1, v2, v3};
#pragma unroll
                for (int c = 0; c < 4; c++) {
                    float xg = vv[c];
                    vv[c] = 0.5f * xg *
                        (1.f + tanhf(0.7978845608028654f * (xg + 0.044715f * xg * xg * xg)));
                }
                o = make_float4(vv[0], vv[1], vv[2], vv[3]);
            } else { // EPI_RESID: out = X + sig * acc
                float4 xv = *(const float4*)(X + row + n);
                o = make_float4(xv.x + sig * v0, xv.y + sig * v1,
                                xv.z + sig * v2, xv.w + sig * v3);
            }
            *(float4*)(C + row + n) = o;
        }
    }
}

// ---------------- chunked complex scan --------------------------------------
// phase 1: local inclusive scan per (b, chunk, n); stores local states + chunk finals
__global__ void scan1_k() {
    int b = blockIdx.y, ch = blockIdx.x, n = threadIdx.x;
    float2 lam = g_lam[n];
    float2 s = make_float2(0.f, 0.f);
    size_t base = ((size_t)(b * L_SZ + ch * CH)) * DS + n;
    for (int i = 0; i < CH; i++) {
        size_t idx = base + (size_t)i * DS;
        float ur = g_Bu_re[idx], ui = g_Bu_im[idx];
        s = make_float2(lam.x * s.x - lam.y * s.y + ur,
                        lam.x * s.y + lam.y * s.x + ui);
        g_sr[idx] = s.x; g_si[idx] = s.y;
    }
    g_final[(b * NCHUNK + ch) * DS + n] = s;
}

// phase 2: combine chunk carries with lam^CH; carry[j] = state entering chunk j
__global__ void scan2_k() {
    int b = blockIdx.x, n = threadIdx.x;
    float2 lam = g_lam[n];
    float2 lc = lam;
#pragma unroll
    for (int t = 0; t < 6; t++) lc = cmul(lc, lc);   // lam^64 (CH = 64 = 2^6)
    float2 c = make_float2(0.f, 0.f);
    for (int j = 0; j < NCHUNK; j++) {
        g_carry[(b * NCHUNK + j) * DS + n] = c;
        float2 f = g_final[(b * NCHUNK + j) * DS + n];
        c = make_float2(lc.x * c.x - lc.y * c.y + f.x,
                        lc.x * c.y + lc.y * c.x + f.y);
    }
}

// phase 3: states[l] = local[l] + lam^(i+1) * carry_in.
// Also writes final state st in PLANAR float32 layout:
//   st_mode == 2 : [B*DS reals][B*DS imags]   (complex split into planes)
//   st_mode == 1 : [B*DS reals] only          (harness kept real part)
__global__ void scan3_k(float* __restrict__ st_out, int st_mode) {
    int b = blockIdx.y, ch = blockIdx.x, n = threadIdx.x;
    float2 lam = g_lam[n];
    float2 c = g_carry[(b * NCHUNK + ch) * DS + n];
    size_t base = ((size_t)(b * L_SZ + ch * CH)) * DS + n;
    float2 p = lam;
    float sr = 0.f, si = 0.f;
    for (int i = 0; i < CH; i++) {
        size_t idx = base + (size_t)i * DS;
        sr = g_sr[idx] + p.x * c.x - p.y * c.y;
        si = g_si[idx] + p.x * c.y + p.y * c.x;
        g_sr[idx] = sr; g_si[idx] = si;
        p = cmul(p, lam);
    }
    if (ch == NCHUNK - 1 && st_mode > 0) {
        st_out[b * DS + n] = sr;                       // real plane
        if (st_mode == 2)
            st_out[B_SZ * DS + b * DS + n] = si;       // imag plane
    }
}

// ---------------- launch ----------------------------------------------------
extern "C" void kernel_launch(void* const* d_in, const int* in_sizes, int n_in,
                              void* d_out, int out_size)
{
    const float* x    = (const float*)d_in[0];
    const float* nu   = (const float*)d_in[1];
    const float* th   = (const float*)d_in[2];
    const float* Bre  = (const float*)d_in[3];
    const float* Bim  = (const float*)d_in[4];
    const float* Cre  = (const float*)d_in[5];
    const float* Cim  = (const float*)d_in[6];
    const float* Dm   = (const float*)d_in[7];
    const float* W1   = (const float*)d_in[8];
    const float* W2   = (const float*)d_in[9];
    const float* rlog = (const float*)d_in[10];
    float* out = (float*)d_out;

    float *bu_re, *bu_im, *sr, *si, *y, *h, *gam;
    cudaGetSymbolAddress((void**)&bu_re, g_Bu_re);
    cudaGetSymbolAddress((void**)&bu_im, g_Bu_im);
    cudaGetSymbolAddress((void**)&sr,    g_sr);
    cudaGetSymbolAddress((void**)&si,    g_si);
    cudaGetSymbolAddress((void**)&y,     g_y);
    cudaGetSymbolAddress((void**)&h,     g_h);
    cudaGetSymbolAddress((void**)&gam,   g_gamma);

    dim3 blk(256);

    precompute_k<<<1, DS>>>(nu, th);

    // Bu = gamma[n] * (x @ B^T)   (two planes: re / im)
    gemm_k<true, EPI_COLSCALE><<<dim3(DS / 128, M_ROWS / 128), blk>>>(
        x, Bre, bu_re, M_ROWS, DS, DM, 1.f, gam, nullptr, nullptr);
    gemm_k<true, EPI_COLSCALE><<<dim3(DS / 128, M_ROWS / 128), blk>>>(
        x, Bim, bu_im, M_ROWS, DS, DM, 1.f, gam, nullptr, nullptr);

    // complex scan along L (exact, 3-phase chunked)
    scan1_k<<<dim3(NCHUNK, B_SZ), DS>>>();
    scan2_k<<<B_SZ, DS>>>();

    // st serialization mode from out_size tail:
    //   tail >= 2*B*DS -> planar re+im; tail >= B*DS -> re only; else skip
    long long tail = (long long)out_size - (long long)M_ROWS * DM;
    int st_mode = (tail >= 2 * B_SZ * DS) ? 2 : (tail >= B_SZ * DS ? 1 : 0);
    float* st_ptr = out + (size_t)M_ROWS * DM;
    scan3_k<<<dim3(NCHUNK, B_SZ), DS>>>(st_ptr, st_mode);

    // y = sr @ C_re^T - si @ C_im^T + x @ D^T
    gemm_k<true, EPI_STORE><<<dim3(DM / 128, M_ROWS / 128), blk>>>(
        sr, Cre, y, M_ROWS, DM, DS, 1.f, nullptr, nullptr, nullptr);
    gemm_k<true, EPI_ADD><<<dim3(DM / 128, M_ROWS / 128), blk>>>(
        si, Cim, y, M_ROWS, DM, DS, -1.f, nullptr, nullptr, nullptr);
    gemm_k<true, EPI_ADD><<<dim3(DM / 128, M_ROWS / 128), blk>>>(
        x, Dm, y, M_ROWS, DM, DM, 1.f, nullptr, nullptr, nullptr);

    // h = gelu(y @ W1)   (NN layout)
    gemm_k<false, EPI_GELU><<<dim3(DH / 128, M_ROWS / 128), blk>>>(
        y, W1, h, M_ROWS, DH, DM, 1.f, nullptr, nullptr, nullptr);

    // out = x + sigmoid(res_logit) * (h @ W2)
    gemm_k<false, EPI_RESID><<<dim3(DM / 128, M_ROWS / 128), blk>>>(
        h, W2, out, M_ROWS, DM, DH, 1.f, nullptr, x, rlog);
}

// round 4
// speedup vs baseline: 3.5477x; 3.5477x over previous
#include <cuda_runtime.h>
#include <math.h>
#include <stdint.h>

// Problem dims (fixed)
#define B_SZ 4
#define L_SZ 4096
#define DM   1024
#define DS   256
#define DH   4096
#define M_ROWS (B_SZ * L_SZ)   // 16384
#define CH     64
#define NCHUNK (L_SZ / CH)     // 64
#define KCAT   1536            // DS + DS + DM

// ---------------- scratch (device globals; no allocations) ------------------
__device__ float  g_Bu  [(size_t)M_ROWS * 512];    // [M, 512]  re|im
__device__ float  g_sr  [(size_t)M_ROWS * DS];
__device__ float  g_si  [(size_t)M_ROWS * DS];
__device__ float  g_Acat[(size_t)M_ROWS * KCAT];   // [M, 1536] sr|si|x(tf32)
__device__ float  g_y   [(size_t)M_ROWS * DM];
__device__ float  g_h   [(size_t)M_ROWS * DH];
__device__ float  g_Bcat[512 * DM];                // [512, 1024] gamma*(Bre;Bim), tf32
__device__ float  g_CD  [DM * KCAT];               // [1024, 1536] Cre|-Cim|D, tf32
__device__ float  g_W1T [(size_t)DH * DM];         // [4096, 1024] tf32
__device__ float  g_W2T [(size_t)DM * DH];         // [1024, 4096] tf32
__device__ float2 g_lam[DS];
__device__ float  g_gamma[DS];
__device__ float2 g_final[B_SZ * NCHUNK * DS];
__device__ float2 g_carry[B_SZ * NCHUNK * DS];

// ---------------- helpers ----------------------------------------------------
__device__ __forceinline__ float rna_tf32(float x) {
    float r;
    asm("cvt.rna.tf32.f32 %0, %1;" : "=f"(r) : "f"(x));
    return r;
}
__device__ __forceinline__ uint32_t smem_u32(const void* p) {
    uint32_t a;
    asm("{ .reg .u64 t; cvta.to.shared.u64 t, %1; cvt.u32.u64 %0, t; }" : "=r"(a) : "l"(p));
    return a;
}
__device__ __forceinline__ void cp_async16(uint32_t saddr, const void* gaddr) {
    asm volatile("cp.async.cg.shared.global [%0], [%1], 16;" :: "r"(saddr), "l"(gaddr));
}
__device__ __forceinline__ void cp_commit() {
    asm volatile("cp.async.commit_group;" ::: "memory");
}
__device__ __forceinline__ void cp_wait1() {
    asm volatile("cp.async.wait_group 1;" ::: "memory");
}
__device__ __forceinline__ void mma_tf32(float* d, const float* a, const float* b) {
    asm volatile(
        "mma.sync.aligned.m16n8k8.row.col.f32.tf32.tf32.f32 "
        "{%0,%1,%2,%3}, {%4,%5,%6,%7}, {%8,%9}, {%0,%1,%2,%3};"
        : "+f"(d[0]), "+f"(d[1]), "+f"(d[2]), "+f"(d[3])
        : "r"(__float_as_uint(a[0])), "r"(__float_as_uint(a[1])),
          "r"(__float_as_uint(a[2])), "r"(__float_as_uint(a[3])),
          "r"(__float_as_uint(b[0])), "r"(__float_as_uint(b[1])));
}

// ---------------- prep kernels ----------------------------------------------
__global__ void precompute_k(const float* __restrict__ nu_log,
                             const float* __restrict__ theta_log) {
    int n = threadIdx.x;
    float nu  = expf(nu_log[n]);
    float th  = expf(theta_log[n]);
    float mag = expf(-nu);
    g_lam[n]   = make_float2(mag * cosf(th), mag * sinf(th));
    g_gamma[n] = sqrtf(fmaxf(0.f, 1.f - mag * mag));
}

__global__ void prep_bcat_k(const float* __restrict__ Bre, const float* __restrict__ Bim) {
    int idx = blockIdx.x * blockDim.x + threadIdx.x;   // over 512*1024
    int n = idx >> 10, k = idx & 1023;
    float v = (n < 256) ? g_gamma[n] * Bre[n * DM + k]
                        : g_gamma[n - 256] * Bim[(n - 256) * DM + k];
    g_Bcat[idx] = rna_tf32(v);
}

__global__ void prep_cd_k(const float* __restrict__ Cre, const float* __restrict__ Cim,
                          const float* __restrict__ Dm) {
    int idx = blockIdx.x * blockDim.x + threadIdx.x;   // over 1024*1536
    int n = idx / KCAT, k = idx - n * KCAT;
    float v;
    if (k < 256)      v =  Cre[n * DS + k];
    else if (k < 512) v = -Cim[n * DS + (k - 256)];
    else              v =  Dm[(size_t)n * DM + (k - 512)];
    g_CD[idx] = rna_tf32(v);
}

__global__ void transpose_k(const float* __restrict__ in, float* __restrict__ out,
                            int R, int Cc) {   // out[c*R+r] = rna(in[r*Cc+c])
    __shared__ float t[32][33];
    int c0 = blockIdx.x * 32, r0 = blockIdx.y * 32;
    int x = threadIdx.x, y0 = threadIdx.y;
    for (int yy = y0; yy < 32; yy += 8)
        t[yy][x] = in[(size_t)(r0 + yy) * Cc + c0 + x];
    __syncthreads();
    for (int yy = y0; yy < 32; yy += 8)
        out[(size_t)(c0 + yy) * R + r0 + x] = rna_tf32(t[x][yy]);
}

__global__ void xcopy_k(const float* __restrict__ x) {  // x -> Acat[:,512:1536] (tf32)
    size_t i = (size_t)blockIdx.x * blockDim.x + threadIdx.x;   // over M*DM/4
    float4 v = ((const float4*)x)[i];
    v.x = rna_tf32(v.x); v.y = rna_tf32(v.y); v.z = rna_tf32(v.z); v.w = rna_tf32(v.w);
    size_t el = i * 4;
    size_t m = el >> 10, c = el & 1023;
    *(float4*)&g_Acat[m * KCAT + 512 + c] = v;
}

// ---------------- tf32 mma.sync GEMM: C[M,N] = A[M,K] @ B[N,K]^T -------------
// 128x128x32 tiles, 3-stage cp.async, 8 warps (4m x 2n), warp tile 32x64.
enum { EPI_F32 = 0, EPI_TF32 = 1, EPI_GELU = 2, EPI_RESID = 3 };

#define BM 128
#define BN 128
#define BK 32
#define STG 3
#define PADK 36                         // 32 + 4 pad -> conflict-free fragments
#define TILE_F (128 * PADK)             // 4608 floats per matrix tile
#define STAGE_F (2 * TILE_F)            // 9216 floats per stage (A then B)
#define SMEM_BYTES (STG * STAGE_F * 4)  // 110592

template<int EPI>
__global__ __launch_bounds__(256)
void mma_gemm(const float* __restrict__ A, const float* __restrict__ Bw,
              float* __restrict__ C, int N, int K, int lda,
              const float* __restrict__ X, const float* __restrict__ res_logit)
{
    extern __shared__ float smf[];
    const int tid  = threadIdx.x;
    const int wid  = tid >> 5, lane = tid & 31;
    const int m0 = blockIdx.y * BM, n0 = blockIdx.x * BN;
    const int wm = (wid & 3) * 32, wn = (wid >> 2) * 64;
    const int r = lane >> 2, cq = lane & 3;

    // loader: thread covers rows lr, lr+32, lr+64, lr+96 at col lc (4 floats)
    const int lr = tid >> 3;
    const int lc = (tid & 7) * 4;
    const float* Ag = A + (size_t)(m0 + lr) * lda + lc;
    const float* Bg = Bw + (size_t)(n0 + lr) * K + lc;
    const uint32_t sbase = smem_u32(smf);
    const uint32_t sAoff = (lr * PADK + lc) * 4;
    const uint32_t sBoff = (TILE_F + lr * PADK + lc) * 4;

    float acc[2][8][4];
#pragma unroll
    for (int mt = 0; mt < 2; mt++)
#pragma unroll
        for (int nt = 0; nt < 8; nt++)
#pragma unroll
            for (int i = 0; i < 4; i++) acc[mt][nt][i] = 0.f;

    const int KT = K / BK;

    // prologue: stages 0..STG-1
#pragma unroll
    for (int s = 0; s < STG; s++) {
        const int k0 = s * BK;
        const uint32_t sb = sbase + s * STAGE_F * 4;
#pragma unroll
        for (int i = 0; i < 4; i++) {
            cp_async16(sb + sAoff + i * 32 * PADK * 4, Ag + k0 + (size_t)i * 32 * lda);
            cp_async16(sb + sBoff + i * 32 * PADK * 4, Bg + k0 + (size_t)i * 32 * K);
        }
        cp_commit();
    }

    for (int kt = 0; kt < KT; kt++) {
        cp_wait1();
        __syncthreads();
        const int buf = kt % STG;
        const float* sA = smf + buf * STAGE_F;
        const float* sB = sA + TILE_F;

#pragma unroll
        for (int ks = 0; ks < 4; ks++) {
            float af[2][4], bf[8][2];
            const int kc = ks * 8 + cq;
#pragma unroll
            for (int mt = 0; mt < 2; mt++) {
                const int ar = wm + mt * 16 + r;
                af[mt][0] = sA[ar * PADK + kc];
                af[mt][1] = sA[(ar + 8) * PADK + kc];
                af[mt][2] = sA[ar * PADK + kc + 4];
                af[mt][3] = sA[(ar + 8) * PADK + kc + 4];
            }
#pragma unroll
            for (int nt = 0; nt < 8; nt++) {
                const int br = wn + nt * 8 + r;
                bf[nt][0] = sB[br * PADK + kc];
                bf[nt][1] = sB[br * PADK + kc + 4];
            }
#pragma unroll
            for (int mt = 0; mt < 2; mt++)
#pragma unroll
                for (int nt = 0; nt < 8; nt++)
                    mma_tf32(acc[mt][nt], af[mt], bf[nt]);
        }
        __syncthreads();

        // issue load for kt+STG into the buffer just freed
        const int kn = kt + STG;
        if (kn < KT) {
            const int k0 = kn * BK;
            const uint32_t sb = sbase + buf * STAGE_F * 4;
#pragma unroll
            for (int i = 0; i < 4; i++) {
                cp_async16(sb + sAoff + i * 32 * PADK * 4, Ag + k0 + (size_t)i * 32 * lda);
                cp_async16(sb + sBoff + i * 32 * PADK * 4, Bg + k0 + (size_t)i * 32 * K);
            }
        }
        cp_commit();
    }

    // epilogue
    float sig = 0.f;
    if (EPI == EPI_RESID) sig = 1.f / (1.f + expf(-res_logit[0]));

#pragma unroll
    for (int mt = 0; mt < 2; mt++) {
#pragma unroll
        for (int nt = 0; nt < 8; nt++) {
            const int row = m0 + wm + mt * 16 + r;
            const int col = n0 + wn + nt * 8 + cq * 2;
#pragma unroll
            for (int h = 0; h < 2; h++) {
                const size_t off = (size_t)(row + h * 8) * N + col;
                float v0 = acc[mt][nt][h * 2 + 0];
                float v1 = acc[mt][nt][h * 2 + 1];
                float2 o;
                if (EPI == EPI_F32) {
                    o = make_float2(v0, v1);
                } else if (EPI == EPI_TF32) {
                    o = make_float2(rna_tf32(v0), rna_tf32(v1));
                } else if (EPI == EPI_GELU) {
                    float g0 = 0.5f * v0 * (1.f + tanhf(0.7978845608028654f * (v0 + 0.044715f * v0 * v0 * v0)));
                    float g1 = 0.5f * v1 * (1.f + tanhf(0.7978845608028654f * (v1 + 0.044715f * v1 * v1 * v1)));
                    o = make_float2(rna_tf32(g0), rna_tf32(g1));
                } else {
                    float2 xv = *(const float2*)(X + off);
                    o = make_float2(xv.x + sig * v0, xv.y + sig * v1);
                }
                *(float2*)(C + off) = o;
            }
        }
    }
}

// ---------------- chunked complex scan (fp32 exact) --------------------------
__device__ __forceinline__ float2 cmul(float2 a, float2 b) {
    return make_float2(a.x * b.x - a.y * b.y, a.x * b.y + a.y * b.x);
}

__global__ void scan1_k() {
    int b = blockIdx.y, chk = blockIdx.x, n = threadIdx.x;
    float2 lam = g_lam[n];
    float2 s = make_float2(0.f, 0.f);
    size_t base = ((size_t)(b * L_SZ + chk * CH)) * 512;
    size_t sbase2 = ((size_t)(b * L_SZ + chk * CH)) * DS + n;
    for (int i = 0; i < CH; i++) {
        size_t ib = base + (size_t)i * 512;
        float ur = g_Bu[ib + n], ui = g_Bu[ib + 256 + n];
        s = make_float2(lam.x * s.x - lam.y * s.y + ur,
                        lam.x * s.y + lam.y * s.x + ui);
        size_t so = sbase2 + (size_t)i * DS;
        g_sr[so] = s.x; g_si[so] = s.y;
    }
    g_final[(b * NCHUNK + chk) * DS + n] = s;
}

__global__ void scan2_k() {
    int b = blockIdx.x, n = threadIdx.x;
    float2 lam = g_lam[n];
    float2 lc = lam;
#pragma unroll
    for (int t = 0; t < 6; t++) lc = cmul(lc, lc);   // lam^64
    float2 c = make_float2(0.f, 0.f);
    for (int j = 0; j < NCHUNK; j++) {
        g_carry[(b * NCHUNK + j) * DS + n] = c;
        float2 f = g_final[(b * NCHUNK + j) * DS + n];
        c = make_float2(lc.x * c.x - lc.y * c.y + f.x,
                        lc.x * c.y + lc.y * c.x + f.y);
    }
}

// writes final states into Acat[:,0:512] (tf32) + st planar (exact fp32)
__global__ void scan3_k(float* __restrict__ st_out, int st_mode) {
    int b = blockIdx.y, chk = blockIdx.x, n = threadIdx.x;
    float2 lam = g_lam[n];
    float2 c = g_carry[(b * NCHUNK + chk) * DS + n];
    size_t sbase2 = ((size_t)(b * L_SZ + chk * CH)) * DS + n;
    size_t abase  = ((size_t)(b * L_SZ + chk * CH)) * KCAT;
    float2 p = lam;
    float sr = 0.f, si = 0.f;
    for (int i = 0; i < CH; i++) {
        size_t so = sbase2 + (size_t)i * DS;
        sr = g_sr[so] + p.x * c.x - p.y * c.y;
        si = g_si[so] + p.x * c.y + p.y * c.x;
        size_t ao = abase + (size_t)i * KCAT;
        g_Acat[ao + n]       = rna_tf32(sr);
        g_Acat[ao + 256 + n] = rna_tf32(si);
        p = cmul(p, lam);
    }
    if (chk == NCHUNK - 1 && st_mode > 0) {
        st_out[b * DS + n] = sr;
        if (st_mode == 2) st_out[B_SZ * DS + b * DS + n] = si;
    }
}

// ---------------- launch ----------------------------------------------------
extern "C" void kernel_launch(void* const* d_in, const int* in_sizes, int n_in,
                              void* d_out, int out_size)
{
    const float* x    = (const float*)d_in[0];
    const float* nu   = (const float*)d_in[1];
    const float* th   = (const float*)d_in[2];
    const float* Bre  = (const float*)d_in[3];
    const float* Bim  = (const float*)d_in[4];
    const float* Cre  = (const float*)d_in[5];
    const float* Cim  = (const float*)d_in[6];
    const float* Dm   = (const float*)d_in[7];
    const float* W1   = (const float*)d_in[8];
    const float* W2   = (const float*)d_in[9];
    const float* rlog = (const float*)d_in[10];
    float* out = (float*)d_out;

    float *bu, *acat, *y, *h, *bcat, *cd, *w1t, *w2t;
    cudaGetSymbolAddress((void**)&bu,   g_Bu);
    cudaGetSymbolAddress((void**)&acat, g_Acat);
    cudaGetSymbolAddress((void**)&y,    g_y);
    cudaGetSymbolAddress((void**)&h,    g_h);
    cudaGetSymbolAddress((void**)&bcat, g_Bcat);
    cudaGetSymbolAddress((void**)&cd,   g_CD);
    cudaGetSymbolAddress((void**)&w1t,  g_W1T);
    cudaGetSymbolAddress((void**)&w2t,  g_W2T);

    cudaFuncSetAttribute(mma_gemm<EPI_F32>,   cudaFuncAttributeMaxDynamicSharedMemorySize, SMEM_BYTES);
    cudaFuncSetAttribute(mma_gemm<EPI_TF32>,  cudaFuncAttributeMaxDynamicSharedMemorySize, SMEM_BYTES);
    cudaFuncSetAttribute(mma_gemm<EPI_GELU>,  cudaFuncAttributeMaxDynamicSharedMemorySize, SMEM_BYTES);
    cudaFuncSetAttribute(mma_gemm<EPI_RESID>, cudaFuncAttributeMaxDynamicSharedMemorySize, SMEM_BYTES);

    precompute_k<<<1, DS>>>(nu, th);
    prep_bcat_k<<<(512 * DM) / 256, 256>>>(Bre, Bim);
    prep_cd_k<<<(DM * KCAT) / 256, 256>>>(Cre, Cim, Dm);
    transpose_k<<<dim3(DH / 32, DM / 32), dim3(32, 8)>>>(W1, w1t, DM, DH);
    transpose_k<<<dim3(DM / 32, DH / 32), dim3(32, 8)>>>(W2, w2t, DH, DM);
    xcopy_k<<<((size_t)M_ROWS * DM / 4) / 256, 256>>>(x);

    // 1) Bu[M,512] = x_tf32 @ Bcat^T   (A = Acat x-slice, lda=1536)
    mma_gemm<EPI_F32><<<dim3(512 / BN, M_ROWS / BM), 256, SMEM_BYTES>>>(
        acat + 512, bcat, bu, 512, DM, KCAT, nullptr, nullptr);

    // 2) scan
    scan1_k<<<dim3(NCHUNK, B_SZ), DS>>>();
    scan2_k<<<B_SZ, DS>>>();
    long long tail = (long long)out_size - (long long)M_ROWS * DM;
    int st_mode = (tail >= 2 * B_SZ * DS) ? 2 : (tail >= B_SZ * DS ? 1 : 0);
    scan3_k<<<dim3(NCHUNK, B_SZ), DS>>>(out + (size_t)M_ROWS * DM, st_mode);

    // 3) y[M,1024] = Acat @ CD^T   (K=1536)
    mma_gemm<EPI_TF32><<<dim3(DM / BN, M_ROWS / BM), 256, SMEM_BYTES>>>(
        acat, cd, y, DM, KCAT, KCAT, nullptr, nullptr);

    // 4) h[M,4096] = gelu(y @ W1T^T)
    mma_gemm<EPI_GELU><<<dim3(DH / BN, M_ROWS / BM), 256, SMEM_BYTES>>>(
        y, w1t, h, DH, DM, DM, nullptr, nullptr);

    // 5) out = x + sigmoid(res_logit) * (h @ W2T^T)
    mma_gemm<EPI_RESID><<<dim3(DM / BN, M_ROWS / BM), 256, SMEM_BYTES>>>(
        h, w2t, out, DM, DH, DH, x, rlog);
}

// round 5
// speedup vs baseline: 3.8413x; 1.0828x over previous
#include <cuda_runtime.h>
#include <math.h>
#include <stdint.h>

// Problem dims (fixed)
#define B_SZ 4
#define L_SZ 4096
#define DM   1024
#define DS   256
#define DH   4096
#define M_ROWS (B_SZ * L_SZ)   // 16384
#define CH     64
#define NCHUNK (L_SZ / CH)     // 64
#define KCAT   1536            // DS + DS + DM

// ---------------- scratch (device globals; no allocations) ------------------
__device__ float  g_Bu  [(size_t)M_ROWS * 512];    // [M, 512]  re|im
__device__ float  g_Acat[(size_t)M_ROWS * KCAT];   // [M, 1536] sr|si|x(tf32)
__device__ float  g_y   [(size_t)M_ROWS * DM];
__device__ float  g_h   [(size_t)M_ROWS * DH];
__device__ float  g_Bcat[512 * DM];                // [512, 1024] gamma*(Bre;Bim), tf32
__device__ float  g_CD  [DM * KCAT];               // [1024, 1536] Cre|-Cim|D, tf32
__device__ float  g_W1T [(size_t)DH * DM];         // [4096, 1024] tf32
__device__ float  g_W2T [(size_t)DM * DH];         // [1024, 4096] tf32
__device__ float2 g_lam[DS];
__device__ float  g_gamma[DS];
__device__ float2 g_final[B_SZ * NCHUNK * DS];
__device__ float2 g_carry[B_SZ * NCHUNK * DS];

// ---------------- helpers ----------------------------------------------------
__device__ __forceinline__ float rna_tf32(float x) {
    float r;
    asm("cvt.rna.tf32.f32 %0, %1;" : "=f"(r) : "f"(x));
    return r;
}
__device__ __forceinline__ uint32_t smem_u32(const void* p) {
    uint32_t a;
    asm("{ .reg .u64 t; cvta.to.shared.u64 t, %1; cvt.u32.u64 %0, t; }" : "=r"(a) : "l"(p));
    return a;
}
__device__ __forceinline__ void cp_async16(uint32_t saddr, const void* gaddr) {
    asm volatile("cp.async.cg.shared.global [%0], [%1], 16;" :: "r"(saddr), "l"(gaddr));
}
__device__ __forceinline__ void cp_commit() {
    asm volatile("cp.async.commit_group;" ::: "memory");
}
__device__ __forceinline__ void cp_wait1() {
    asm volatile("cp.async.wait_group 1;" ::: "memory");
}
__device__ __forceinline__ void mma_tf32(float* d, const float* a, const float* b) {
    asm volatile(
        "mma.sync.aligned.m16n8k8.row.col.f32.tf32.tf32.f32 "
        "{%0,%1,%2,%3}, {%4,%5,%6,%7}, {%8,%9}, {%0,%1,%2,%3};"
        : "+f"(d[0]), "+f"(d[1]), "+f"(d[2]), "+f"(d[3])
        : "r"(__float_as_uint(a[0])), "r"(__float_as_uint(a[1])),
          "r"(__float_as_uint(a[2])), "r"(__float_as_uint(a[3])),
          "r"(__float_as_uint(b[0])), "r"(__float_as_uint(b[1])));
}

// ---------------- prep kernels ----------------------------------------------
__global__ void precompute_k(const float* __restrict__ nu_log,
                             const float* __restrict__ theta_log) {
    int n = threadIdx.x;
    float nu  = expf(nu_log[n]);
    float th  = expf(theta_log[n]);
    float mag = expf(-nu);
    g_lam[n]   = make_float2(mag * cosf(th), mag * sinf(th));
    g_gamma[n] = sqrtf(fmaxf(0.f, 1.f - mag * mag));
}

__global__ void prep_bcat_k(const float* __restrict__ Bre, const float* __restrict__ Bim) {
    int idx = blockIdx.x * blockDim.x + threadIdx.x;   // over 512*1024
    int n = idx >> 10, k = idx & 1023;
    float v = (n < 256) ? g_gamma[n] * Bre[n * DM + k]
                        : g_gamma[n - 256] * Bim[(n - 256) * DM + k];
    g_Bcat[idx] = rna_tf32(v);
}

__global__ void prep_cd_k(const float* __restrict__ Cre, const float* __restrict__ Cim,
                          const float* __restrict__ Dm) {
    int idx = blockIdx.x * blockDim.x + threadIdx.x;   // over 1024*1536
    int n = idx / KCAT, k = idx - n * KCAT;
    float v;
    if (k < 256)      v =  Cre[n * DS + k];
    else if (k < 512) v = -Cim[n * DS + (k - 256)];
    else              v =  Dm[(size_t)n * DM + (k - 512)];
    g_CD[idx] = rna_tf32(v);
}

__global__ void transpose_k(const float* __restrict__ in, float* __restrict__ out,
                            int R, int Cc) {   // out[c*R+r] = rna(in[r*Cc+c])
    __shared__ float t[32][33];
    int c0 = blockIdx.x * 32, r0 = blockIdx.y * 32;
    int x = threadIdx.x, y0 = threadIdx.y;
    for (int yy = y0; yy < 32; yy += 8)
        t[yy][x] = in[(size_t)(r0 + yy) * Cc + c0 + x];
    __syncthreads();
    for (int yy = y0; yy < 32; yy += 8)
        out[(size_t)(c0 + yy) * R + r0 + x] = rna_tf32(t[x][yy]);
}

__global__ void xcopy_k(const float* __restrict__ x) {  // x -> Acat[:,512:1536] (tf32)
    size_t i = (size_t)blockIdx.x * blockDim.x + threadIdx.x;   // over M*DM/4
    float4 v = ((const float4*)x)[i];
    v.x = rna_tf32(v.x); v.y = rna_tf32(v.y); v.z = rna_tf32(v.z); v.w = rna_tf32(v.w);
    size_t el = i * 4;
    size_t m = el >> 10, c = el & 1023;
    *(float4*)&g_Acat[m * KCAT + 512 + c] = v;
}

// ---------------- tf32 mma.sync GEMM: C[M,N] = A[M,K] @ B[N,K]^T -------------
// 128x128x32 tiles, 3-stage cp.async, single-sync mainloop, 8 warps (4m x 2n).
enum { EPI_F32 = 0, EPI_TF32 = 1, EPI_GELU = 2, EPI_RESID = 3 };

#define BM 128
#define BN 128
#define BK 32
#define STG 3
#define PADK 36                         // 32 + 4 pad -> conflict-free fragments
#define TILE_F (128 * PADK)             // 4608 floats per matrix tile
#define STAGE_F (2 * TILE_F)            // 9216 floats per stage (A then B)
#define SMEM_BYTES (STG * STAGE_F * 4)  // 110592 -> 2 CTAs/SM (216KB of 228KB)

template<int EPI>
__global__ __launch_bounds__(256, 2)
void mma_gemm(const float* __restrict__ A, const float* __restrict__ Bw,
              float* __restrict__ C, int N, int K, int lda,
              const float* __restrict__ X, const float* __restrict__ res_logit)
{
    extern __shared__ float smf[];
    const int tid  = threadIdx.x;
    const int wid  = tid >> 5, lane = tid & 31;
    const int m0 = blockIdx.y * BM, n0 = blockIdx.x * BN;
    const int wm = (wid & 3) * 32, wn = (wid >> 2) * 64;
    const int r = lane >> 2, cq = lane & 3;

    // loader: thread covers rows lr, lr+32, lr+64, lr+96 at col lc (4 floats)
    const int lr = tid >> 3;
    const int lc = (tid & 7) * 4;
    const float* Ag = A + (size_t)(m0 + lr) * lda + lc;
    const float* Bg = Bw + (size_t)(n0 + lr) * K + lc;
    const uint32_t sbase = smem_u32(smf);
    const uint32_t sAoff = (lr * PADK + lc) * 4;
    const uint32_t sBoff = (TILE_F + lr * PADK + lc) * 4;

    float acc[2][8][4];
#pragma unroll
    for (int mt = 0; mt < 2; mt++)
#pragma unroll
        for (int nt = 0; nt < 8; nt++)
#pragma unroll
            for (int i = 0; i < 4; i++) acc[mt][nt][i] = 0.f;

    const int KT = K / BK;

    // prologue: stages 0..STG-2 (one group each)
#pragma unroll
    for (int s = 0; s < STG - 1; s++) {
        const int k0 = s * BK;
        const uint32_t sb = sbase + s * STAGE_F * 4;
#pragma unroll
        for (int i = 0; i < 4; i++) {
            cp_async16(sb + sAoff + i * 32 * PADK * 4, Ag + k0 + (size_t)i * 32 * lda);
            cp_async16(sb + sBoff + i * 32 * PADK * 4, Bg + k0 + (size_t)i * 32 * K);
        }
        cp_commit();
    }

    for (int kt = 0; kt < KT; kt++) {
        cp_wait1();           // stage kt resident (<= STG-2 groups outstanding)
        __syncthreads();      // all threads done computing kt-1; slot (kt-1)%STG free

        // prefetch stage kt+STG-1 into slot (kt+STG-1)%STG == (kt-1)%STG
        const int kp = kt + STG - 1;
        if (kp < KT) {
            const int k0 = kp * BK;
            const uint32_t sb = sbase + (kp % STG) * STAGE_F * 4;
#pragma unroll
            for (int i = 0; i < 4; i++) {
                cp_async16(sb + sAoff + i * 32 * PADK * 4, Ag + k0 + (size_t)i * 32 * lda);
                cp_async16(sb + sBoff + i * 32 * PADK * 4, Bg + k0 + (size_t)i * 32 * K);
            }
        }
        cp_commit();          // commit even when empty to keep group count in step

        const float* sA = smf + (kt % STG) * STAGE_F;
        const float* sB = sA + TILE_F;
#pragma unroll
        for (int ks = 0; ks < 4; ks++) {
            float af[2][4], bf[8][2];
            const int kc = ks * 8 + cq;
#pragma unroll
            for (int mt = 0; mt < 2; mt++) {
                const int ar = wm + mt * 16 + r;
                af[mt][0] = sA[ar * PADK + kc];
                af[mt][1] = sA[(ar + 8) * PADK + kc];
                af[mt][2] = sA[ar * PADK + kc + 4];
                af[mt][3] = sA[(ar + 8) * PADK + kc + 4];
            }
#pragma unroll
            for (int nt = 0; nt < 8; nt++) {
                const int br = wn + nt * 8 + r;
                bf[nt][0] = sB[br * PADK + kc];
                bf[nt][1] = sB[br * PADK + kc + 4];
            }
#pragma unroll
            for (int mt = 0; mt < 2; mt++)
#pragma unroll
                for (int nt = 0; nt < 8; nt++)
                    mma_tf32(acc[mt][nt], af[mt], bf[nt]);
        }
    }

    // epilogue
    float sig = 0.f;
    if (EPI == EPI_RESID) sig = 1.f / (1.f + expf(-res_logit[0]));

#pragma unroll
    for (int mt = 0; mt < 2; mt++) {
#pragma unroll
        for (int nt = 0; nt < 8; nt++) {
            const int row = m0 + wm + mt * 16 + r;
            const int col = n0 + wn + nt * 8 + cq * 2;
#pragma unroll
            for (int h = 0; h < 2; h++) {
                const size_t off = (size_t)(row + h * 8) * N + col;
                float v0 = acc[mt][nt][h * 2 + 0];
                float v1 = acc[mt][nt][h * 2 + 1];
                float2 o;
                if (EPI == EPI_F32) {
                    o = make_float2(v0, v1);
                } else if (EPI == EPI_TF32) {
                    o = make_float2(rna_tf32(v0), rna_tf32(v1));
                } else if (EPI == EPI_GELU) {
                    float g0 = 0.5f * v0 * (1.f + tanhf(0.7978845608028654f * (v0 + 0.044715f * v0 * v0 * v0)));
                    float g1 = 0.5f * v1 * (1.f + tanhf(0.7978845608028654f * (v1 + 0.044715f * v1 * v1 * v1)));
                    o = make_float2(rna_tf32(g0), rna_tf32(g1));
                } else {
                    float2 xv = *(const float2*)(X + off);
                    o = make_float2(xv.x + sig * v0, xv.y + sig * v1);
                }
                *(float2*)(C + off) = o;
            }
        }
    }
}

// ---------------- chunked complex scan (fp32 exact) --------------------------
__device__ __forceinline__ float2 cmul(float2 a, float2 b) {
    return make_float2(a.x * b.x - a.y * b.y, a.x * b.y + a.y * b.x);
}

// phase 1: chunk-local finals only (no per-step stores)
__global__ void scan1_k() {
    int b = blockIdx.y, chk = blockIdx.x, n = threadIdx.x;
    float2 lam = g_lam[n];
    float2 s = make_float2(0.f, 0.f);
    size_t base = ((size_t)(b * L_SZ + chk * CH)) * 512;
    for (int i = 0; i < CH; i++) {
        size_t ib = base + (size_t)i * 512;
        float ur = g_Bu[ib + n], ui = g_Bu[ib + 256 + n];
        s = make_float2(lam.x * s.x - lam.y * s.y + ur,
                        lam.x * s.y + lam.y * s.x + ui);
    }
    g_final[(b * NCHUNK + chk) * DS + n] = s;
}

// phase 2: combine chunk carries with lam^CH
__global__ void scan2_k() {
    int b = blockIdx.x, n = threadIdx.x;
    float2 lam = g_lam[n];
    float2 lc = lam;
#pragma unroll
    for (int t = 0; t < 6; t++) lc = cmul(lc, lc);   // lam^64
    float2 c = make_float2(0.f, 0.f);
    for (int j = 0; j < NCHUNK; j++) {
        g_carry[(b * NCHUNK + j) * DS + n] = c;
        float2 f = g_final[(b * NCHUNK + j) * DS + n];
        c = make_float2(lc.x * c.x - lc.y * c.y + f.x,
                        lc.x * c.y + lc.y * c.x + f.y);
    }
}

// phase 3: re-run the scan seeded with the carry (exact sequential order),
// writing tf32 states into Acat[:,0:512] + exact fp32 final st (planar).
__global__ void scan3_k(float* __restrict__ st_out, int st_mode) {
    int b = blockIdx.y, chk = blockIdx.x, n = threadIdx.x;
    float2 lam = g_lam[n];
    float2 s = g_carry[(b * NCHUNK + chk) * DS + n];
    size_t base  = ((size_t)(b * L_SZ + chk * CH)) * 512;
    size_t abase = ((size_t)(b * L_SZ + chk * CH)) * KCAT;
    for (int i = 0; i < CH; i++) {
        size_t ib = base + (size_t)i * 512;
        float ur = g_Bu[ib + n], ui = g_Bu[ib + 256 + n];
        s = make_float2(lam.x * s.x - lam.y * s.y + ur,
                        lam.x * s.y + lam.y * s.x + ui);
        size_t ao = abase + (size_t)i * KCAT;
        g_Acat[ao + n]       = rna_tf32(s.x);
        g_Acat[ao + 256 + n] = rna_tf32(s.y);
    }
    if (chk == NCHUNK - 1 && st_mode > 0) {
        st_out[b * DS + n] = s.x;
        if (st_mode == 2) st_out[B_SZ * DS + b * DS + n] = s.y;
    }
}

// ---------------- launch ----------------------------------------------------
extern "C" void kernel_launch(void* const* d_in, const int* in_sizes, int n_in,
                              void* d_out, int out_size)
{
    const float* x    = (const float*)d_in[0];
    const float* nu   = (const float*)d_in[1];
    const float* th   = (const float*)d_in[2];
    const float* Bre  = (const float*)d_in[3];
    const float* Bim  = (const float*)d_in[4];
    const float* Cre  = (const float*)d_in[5];
    const float* Cim  = (const float*)d_in[6];
    const float* Dm   = (const float*)d_in[7];
    const float* W1   = (const float*)d_in[8];
    const float* W2   = (const float*)d_in[9];
    const float* rlog = (const float*)d_in[10];
    float* out = (float*)d_out;

    float *bu, *acat, *y, *h, *bcat, *cd, *w1t, *w2t;
    cudaGetSymbolAddress((void**)&bu,   g_Bu);
    cudaGetSymbolAddress((void**)&acat, g_Acat);
    cudaGetSymbolAddress((void**)&y,    g_y);
    cudaGetSymbolAddress((void**)&h,    g_h);
    cudaGetSymbolAddress((void**)&bcat, g_Bcat);
    cudaGetSymbolAddress((void**)&cd,   g_CD);
    cudaGetSymbolAddress((void**)&w1t,  g_W1T);
    cudaGetSymbolAddress((void**)&w2t,  g_W2T);

    cudaFuncSetAttribute(mma_gemm<EPI_F32>,   cudaFuncAttributeMaxDynamicSharedMemorySize, SMEM_BYTES);
    cudaFuncSetAttribute(mma_gemm<EPI_TF32>,  cudaFuncAttributeMaxDynamicSharedMemorySize, SMEM_BYTES);
    cudaFuncSetAttribute(mma_gemm<EPI_GELU>,  cudaFuncAttributeMaxDynamicSharedMemorySize, SMEM_BYTES);
    cudaFuncSetAttribute(mma_gemm<EPI_RESID>, cudaFuncAttributeMaxDynamicSharedMemorySize, SMEM_BYTES);

    precompute_k<<<1, DS>>>(nu, th);
    prep_bcat_k<<<(512 * DM) / 256, 256>>>(Bre, Bim);
    prep_cd_k<<<(DM * KCAT) / 256, 256>>>(Cre, Cim, Dm);
    transpose_k<<<dim3(DH / 32, DM / 32), dim3(32, 8)>>>(W1, w1t, DM, DH);
    transpose_k<<<dim3(DM / 32, DH / 32), dim3(32, 8)>>>(W2, w2t, DH, DM);
    xcopy_k<<<((size_t)M_ROWS * DM / 4) / 256, 256>>>(x);

    // 1) Bu[M,512] = x_tf32 @ Bcat^T   (A = Acat x-slice, lda=1536)
    mma_gemm<EPI_F32><<<dim3(512 / BN, M_ROWS / BM), 256, SMEM_BYTES>>>(
        acat + 512, bcat, bu, 512, DM, KCAT, nullptr, nullptr);

    // 2) scan (exact fp32)
    scan1_k<<<dim3(NCHUNK, B_SZ), DS>>>();
    scan2_k<<<B_SZ, DS>>>();
    long long tail = (long long)out_size - (long long)M_ROWS * DM;
    int st_mode = (tail >= 2 * B_SZ * DS) ? 2 : (tail >= B_SZ * DS ? 1 : 0);
    scan3_k<<<dim3(NCHUNK, B_SZ), DS>>>(out + (size_t)M_ROWS * DM, st_mode);

    // 3) y[M,1024] = Acat @ CD^T   (K=1536)
    mma_gemm<EPI_TF32><<<dim3(DM / BN, M_ROWS / BM), 256, SMEM_BYTES>>>(
        acat, cd, y, DM, KCAT, KCAT, nullptr, nullptr);

    // 4) h[M,4096] = gelu(y @ W1T^T)
    mma_gemm<EPI_GELU><<<dim3(DH / BN, M_ROWS / BM), 256, SMEM_BYTES>>>(
        y, w1t, h, DH, DM, DM, nullptr, nullptr);

    // 5) out = x + sigmoid(res_logit) * (h @ W2T^T)
    mma_gemm<EPI_RESID><<<dim3(DM / BN, M_ROWS / BM), 256, SMEM_BYTES>>>(
        h, w2t, out, DM, DH, DH, x, rlog);
}